// round 13
// baseline (speedup 1.0000x reference)
#include <cuda_runtime.h>
#include <math.h>

// SpatialGradient: depthwise 3x3 Sobel, zero SAME padding, [B,C,H,W]=[8,32,512,512] fp32.
// direction<0 -> |gx| ; direction>0 -> |gy| ; direction==0 -> sqrt(gx^2+gy^2).
// 4-wide x 8-row per thread, 3-row register sliding window, software-pipelined row
// prefetch (distance 2). Narrow tile cuts regs so 5 CTAs/SM fit (40 warps, 62.5% occ)
// while each warp keeps 2 rows of LDGs in flight -> in-flight bytes/SM ~41KB > 25KB req.
// Warp covers 128 contiguous columns of one row; horizontal halo via warp shuffle.
// Streaming (.cs) output stores. Block 32x8 covers a 128x64 tile.

#define H_DIM 512
#define W_DIM 512
#define ROWS_PER_THREAD 8

__device__ int g_zero_dir = 0;   // fallback if direction input is absent

__device__ __forceinline__ float sqrt_approx(float x) {
    float y;
    asm("sqrt.approx.f32 %0, %1;" : "=f"(y) : "f"(x));
    return y;
}

struct Pre {
    float4 c;
    float  edge;    // left halo for lane 0, right halo for lane 31
};

// Issue the loads for one row-segment (no dependent ops -> LDGs go in flight).
__device__ __forceinline__ Pre fetch_row(const float* __restrict__ p,
                                         int yy, int x0, int lane)
{
    Pre f;
    const bool valid = (yy >= 0) && (yy < H_DIM);   // warp-uniform
    f.edge = 0.0f;
    if (valid) {
        const float* row = p + yy * W_DIM + x0;
        f.c = *(const float4*)row;          // x0 is 16B-aligned
        if (lane == 0  && x0 > 0)          f.edge = __ldg(row - 1);
        if (lane == 31 && x0 + 4 < W_DIM)  f.edge = __ldg(row + 4);
    } else {
        f.c = make_float4(0.f, 0.f, 0.f, 0.f);
    }
    return f;
}

// Consume a fetched row: unpack + exchange horizontal halo via shuffle.
__device__ __forceinline__ void finish_row(const Pre& f, int lane, float r[6])
{
    r[1] = f.c.x; r[2] = f.c.y; r[3] = f.c.z; r[4] = f.c.w;

    float left  = __shfl_up_sync(0xffffffffu, r[4], 1);   // lane i-1's col x0-1
    float right = __shfl_down_sync(0xffffffffu, r[1], 1); // lane i+1's col x0+4
    if (lane == 0)  left  = f.edge;
    if (lane == 31) right = f.edge;
    r[0] = left;
    r[5] = right;
}

__global__ __launch_bounds__(256, 5) void sobel_kernel(
    const float* __restrict__ in,
    const int*   __restrict__ dir_p,
    float*       __restrict__ out)
{
    const int lane = threadIdx.x;                            // 0..31 (one warp per row)
    const int ty   = threadIdx.y;                            // 0..7
    const int x0 = blockIdx.x * 128 + lane * 4;              // first output column
    const int y0 = (blockIdx.y * 8 + ty) * ROWS_PER_THREAD;  // first output row
    const long long img = blockIdx.z;

    const float* p = in  + img * (long long)(H_DIM * W_DIM);
    float*       q = out + img * (long long)(H_DIM * W_DIM);

    const int dir = *dir_p;  // uniform broadcast

    float a[6], b[6], c[6];    // rows y-1, y, y+1 (rolling)
    {
        Pre fa = fetch_row(p, y0 - 1, x0, lane);
        Pre fb = fetch_row(p, y0,     x0, lane);
        finish_row(fa, lane, a);
        finish_row(fb, lane, b);
    }
    Pre f1 = fetch_row(p, y0 + 1, x0, lane);   // row y0+1 in flight
    Pre f2 = fetch_row(p, y0 + 2, x0, lane);   // row y0+2 in flight

    #pragma unroll
    for (int rr = 0; rr < ROWS_PER_THREAD; rr++) {
        const int y = y0 + rr;

        // Prefetch row y+3 (statically elided on the last two iterations).
        Pre fn;
        if (rr < ROWS_PER_THREAD - 2)
            fn = fetch_row(p, y + 3, x0, lane);

        finish_row(f1, lane, c);   // waits on row y+1's loads

        // Separable vertical pass: smooth (for gx) and diff (for gy), per column.
        float t[6], d[6];
        #pragma unroll
        for (int k = 0; k < 6; k++) {
            t[k] = fmaf(2.0f, b[k], a[k]) + c[k];   // a + 2b + c
            d[k] = c[k] - a[k];                     // c - a
        }

        float res[4];
        #pragma unroll
        for (int j = 0; j < 4; j++) {
            const float gx = t[j+2] - t[j];
            const float gy = fmaf(2.0f, d[j+1], d[j]) + d[j+2];
            float v;
            if (dir < 0)      v = fabsf(gx);
            else if (dir > 0) v = fabsf(gy);
            else              v = sqrt_approx(fmaf(gx, gx, gy * gy));
            res[j] = v;
        }

        __stcs((float4*)(q + y * W_DIM + x0),
               make_float4(res[0], res[1], res[2], res[3]));

        // rotate window and pipeline regs (renamed away by ptxas after full unroll)
        #pragma unroll
        for (int j = 0; j < 6; j++) { a[j] = b[j]; b[j] = c[j]; }
        f1 = f2;
        if (rr < ROWS_PER_THREAD - 2)
            f2 = fn;
    }
}

extern "C" void kernel_launch(void* const* d_in, const int* in_sizes, int n_in,
                              void* d_out, int out_size)
{
    const float* input = (const float*)d_in[0];
    float*       outp  = (float*)d_out;

    const int* dir;
    if (n_in >= 2) {
        dir = (const int*)d_in[1];
    } else {
        int* dz;
        cudaGetSymbolAddress((void**)&dz, g_zero_dir);
        dir = dz;
    }

    const int n_imgs = in_sizes[0] / (H_DIM * W_DIM);   // B*C = 256

    dim3 block(32, 8, 1);
    dim3 grid(W_DIM / 128, H_DIM / (8 * ROWS_PER_THREAD), n_imgs);  // (4, 8, 256)
    sobel_kernel<<<grid, block>>>(input, dir, outp);
}